// round 6
// baseline (speedup 1.0000x reference)
#include <cuda_runtime.h>

#define BB 32
#define NN 4096
#define DD 1024
#define HH 16

// Scratch (device globals)
__device__ float g_qp[4][BB * DD];          // q projection partials over 4 d-ranges
__device__ float g_Ut[BB * DD * HH];        // folded key vectors, transposed [b][d][h] (scaled 1/8)
__device__ float g_attp[2][BB * HH * NN];   // partial scores per d-half
__device__ float g_att[BB * HH * NN];       // attn (softmaxed)
__device__ float g_wp[16][BB * HH * DD];    // partial attn@value over 16 n-segments

typedef unsigned long long u64;

__device__ __forceinline__ void fma2(u64 &d, u64 a, u64 b) {
    asm("fma.rn.f32x2 %0, %1, %2, %0;" : "+l"(d) : "l"(a), "l"(b));
}
__device__ __forceinline__ u64 pack2(float lo, float hi) {
    u64 r; asm("mov.b64 %0, {%1, %2};" : "=l"(r) : "f"(lo), "f"(hi)); return r;
}
__device__ __forceinline__ void unpack2(u64 v, float &lo, float &hi) {
    asm("mov.b64 {%0, %1}, %2;" : "=f"(lo), "=f"(hi) : "l"(v));
}
__device__ __forceinline__ unsigned smem_u32(const void* p) {
    return (unsigned)__cvta_generic_to_shared(p);
}
__device__ __forceinline__ void cpasync16(unsigned dst, const void* src) {
    asm volatile("cp.async.cg.shared.global [%0], [%1], 16;\n" :: "r"(dst), "l"(src));
}
#define CP_COMMIT() asm volatile("cp.async.commit_group;\n" ::: "memory")
#define CP_WAIT(n)  asm volatile("cp.async.wait_group %0;\n" :: "n"(n) : "memory")

// ---------------------------------------------------------------------------
// Kernel A: qp[dsp][b,c] = sum_{d in dsp-range(256)} query[b,d] * wq[d,c]
// ---------------------------------------------------------------------------
__global__ __launch_bounds__(128) void k_qproj(const float* __restrict__ query,
                                               const float* __restrict__ wq) {
    const int tx  = threadIdx.x;
    const int c0  = blockIdx.x * 128;
    const int b0  = blockIdx.y * 4;
    const int dsp = blockIdx.z;
    const int dr0 = dsp * 256;

    __shared__ __align__(16) float sq[4][256];
#pragma unroll
    for (int i = 0; i < 2; i++) {
        int fl = i * 128 + tx;
        int bb = fl >> 6, d4 = fl & 63;
        *(float4*)&sq[bb][d4 * 4] =
            *(const float4*)(query + (size_t)(b0 + bb) * DD + dr0 + d4 * 4);
    }
    __syncthreads();

    u64 acc[4] = {0ull, 0ull, 0ull, 0ull};
    const float* wc = wq + (size_t)dr0 * DD + c0 + tx;
#pragma unroll 8
    for (int d = 0; d < 256; d += 2) {
        float w0 = wc[(size_t)d * DD];
        float w1 = wc[(size_t)(d + 1) * DD];
        u64 w2 = pack2(w0, w1);
#pragma unroll
        for (int bb = 0; bb < 4; bb++) {
            u64 q2 = *(const u64*)&sq[bb][d];
            fma2(acc[bb], q2, w2);
        }
    }
#pragma unroll
    for (int bb = 0; bb < 4; bb++) {
        float lo, hi; unpack2(acc[bb], lo, hi);
        g_qp[dsp][(size_t)(b0 + bb) * DD + c0 + tx] = lo + hi;
    }
}

// ---------------------------------------------------------------------------
// Kernel B: Ut[b,d,h] = (1/8) * sum_{c<64} wk[d, h*64+c] * q[b, h*64+c]
// ---------------------------------------------------------------------------
__global__ __launch_bounds__(128) void k_uproj(const float* __restrict__ wk) {
    const int tx = threadIdx.x;
    const int d0 = blockIdx.x * 128;
    const int h  = blockIdx.y;
    __shared__ __align__(16) float4 swk4[128 * 17];
    __shared__ __align__(16) float  sq[32][64];

#pragma unroll
    for (int i = 0; i < 16; i++) {
        int fl = i * 128 + tx;
        int r  = fl >> 4, c4 = fl & 15;
        swk4[r * 17 + c4] =
            *(const float4*)(wk + (size_t)(d0 + r) * DD + h * 64 + c4 * 4);
    }
#pragma unroll
    for (int i = 0; i < 4; i++) {
        int fl = i * 128 + tx;
        int bb = fl >> 4, c4 = fl & 15;
        float4 s = *(const float4*)(g_qp[0] + (size_t)bb * DD + h * 64 + c4 * 4);
#pragma unroll
        for (int p = 1; p < 4; p++) {
            float4 a = *(const float4*)(g_qp[p] + (size_t)bb * DD + h * 64 + c4 * 4);
            s.x += a.x; s.y += a.y; s.z += a.z; s.w += a.w;
        }
        *(float4*)&sq[bb][c4 * 4] = s;
    }
    __syncthreads();

    ulonglong2 wreg[16];
#pragma unroll
    for (int c4 = 0; c4 < 16; c4++)
        wreg[c4] = *(const ulonglong2*)&swk4[tx * 17 + c4];

    const int dst_base = (d0 + tx) * HH + h;
#pragma unroll 2
    for (int bb = 0; bb < 32; bb++) {
        u64 a2 = 0ull;
#pragma unroll
        for (int c4 = 0; c4 < 16; c4++) {
            ulonglong2 q2 = *(const ulonglong2*)&sq[bb][c4 * 4];
            fma2(a2, wreg[c4].x, q2.x);
            fma2(a2, wreg[c4].y, q2.y);
        }
        float lo, hi; unpack2(a2, lo, hi);
        g_Ut[(size_t)bb * (DD * HH) + dst_base] = (lo + hi) * 0.125f;
    }
}

// ---------------------------------------------------------------------------
// Kernel Z: zero d_out (keeps k_scores in the profiled launch slot #4).
// ---------------------------------------------------------------------------
__global__ __launch_bounds__(256) void k_zero(float* __restrict__ out) {
    int i = blockIdx.x * 256 + threadIdx.x;
    reinterpret_cast<float4*>(out)[i] = make_float4(0.f, 0.f, 0.f, 0.f);
}

// ---------------------------------------------------------------------------
// Kernel C: partial scores over one 512-d half.
// attp[dh][b,h,n] = sum_{d in half} key[b,n,d] * Ut[b,d,h]
// grid (16 n-tiles, 2 d-halves, 32 b) = 1024 CTAs, 128 thr, 4 warps.
// Per-warp private 64-n slabs, d-chunk 8, 2-stage cp.async, warp-sync only.
// smem 28KB, launch_bounds(128,5) -> ~20 warps/SM.
// ---------------------------------------------------------------------------
__global__ __launch_bounds__(128, 5) void k_scores(const float* __restrict__ key) {
    const int tx   = threadIdx.x;
    const int w    = tx >> 5;
    const int l    = tx & 31;
    const int b    = blockIdx.z;
    const int dh   = blockIdx.y;
    const int n0   = blockIdx.x * 256;
    const int nwrp = n0 + w * 64;

    // key slab: [64 n][2 data f4 + 1 pad] -> stride 3 f4: 3l mod 8 covers all
    // bank phases -> conflict-free LDS.128. 24KB total.
    __shared__ __align__(16) float4 skW[4][2][64 * 3];
    // U chunk: [8 d][16 h] floats = 32 f4 per stage per warp. 4KB total.
    __shared__ __align__(16) float4 sUW[4][2][32];

    const float* keyw = key + ((size_t)b * NN + nwrp) * DD + dh * 512;
    const float* Utb  = g_Ut + (size_t)b * (DD * HH) + dh * 512 * HH;

    u64 acc_a[8], acc_b[8];
#pragma unroll
    for (int p = 0; p < 8; p++) { acc_a[p] = 0ull; acc_b[p] = 0ull; }

    // prologue: stage chunk 0
    {
#pragma unroll
        for (int i = 0; i < 4; i++) {
            int fl = i * 32 + l;
            int n = fl >> 1, q4 = fl & 1;
            cpasync16(smem_u32(&skW[w][0][n * 3 + q4]),
                      keyw + (size_t)n * DD + q4 * 4);
        }
        cpasync16(smem_u32(&sUW[w][0][l]), Utb + l * 4);
        CP_COMMIT();
    }

#pragma unroll 1
    for (int ch = 0; ch < 64; ch++) {
        if (ch + 1 < 64) {
            const int st = (ch + 1) & 1, d0 = (ch + 1) * 8;
#pragma unroll
            for (int i = 0; i < 4; i++) {
                int fl = i * 32 + l;
                int n = fl >> 1, q4 = fl & 1;
                cpasync16(smem_u32(&skW[w][st][n * 3 + q4]),
                          keyw + (size_t)n * DD + d0 + q4 * 4);
            }
            cpasync16(smem_u32(&sUW[w][st][l]), Utb + d0 * HH + l * 4);
            CP_COMMIT();
            CP_WAIT(1);
        } else {
            CP_WAIT(0);
        }
        __syncwarp();

        const int st = ch & 1;
        float4 ka0 = skW[w][st][l * 3 + 0];
        float4 ka1 = skW[w][st][l * 3 + 1];
        float4 kb0 = skW[w][st][(l + 32) * 3 + 0];
        float4 kb1 = skW[w][st][(l + 32) * 3 + 1];
        float kas[8] = {ka0.x, ka0.y, ka0.z, ka0.w, ka1.x, ka1.y, ka1.z, ka1.w};
        float kbs[8] = {kb0.x, kb0.y, kb0.z, kb0.w, kb1.x, kb1.y, kb1.z, kb1.w};
#pragma unroll
        for (int dd = 0; dd < 8; dd++) {
            u64 kva = pack2(kas[dd], kas[dd]);
            u64 kvb = pack2(kbs[dd], kbs[dd]);
            const ulonglong2* uv = (const ulonglong2*)&sUW[w][st][dd * 4];
            ulonglong2 u0 = uv[0], u1 = uv[1];
            fma2(acc_a[0], u0.x, kva);  fma2(acc_b[0], u0.x, kvb);
            fma2(acc_a[1], u0.y, kva);  fma2(acc_b[1], u0.y, kvb);
            fma2(acc_a[2], u1.x, kva);  fma2(acc_b[2], u1.x, kvb);
            fma2(acc_a[3], u1.y, kva);  fma2(acc_b[3], u1.y, kvb);
            ulonglong2 u2 = uv[2], u3 = uv[3];
            fma2(acc_a[4], u2.x, kva);  fma2(acc_b[4], u2.x, kvb);
            fma2(acc_a[5], u2.y, kva);  fma2(acc_b[5], u2.y, kvb);
            fma2(acc_a[6], u3.x, kva);  fma2(acc_b[6], u3.x, kvb);
            fma2(acc_a[7], u3.y, kva);  fma2(acc_b[7], u3.y, kvb);
        }
        __syncwarp();
    }

    float* dst = g_attp[dh];
#pragma unroll
    for (int p = 0; p < 8; p++) {
        float lo, hi;
        unpack2(acc_a[p], lo, hi);
        dst[((size_t)b * HH + 2 * p)     * NN + nwrp + l] = lo;
        dst[((size_t)b * HH + 2 * p + 1) * NN + nwrp + l] = hi;
        unpack2(acc_b[p], lo, hi);
        dst[((size_t)b * HH + 2 * p)     * NN + nwrp + 32 + l] = lo;
        dst[((size_t)b * HH + 2 * p + 1) * NN + nwrp + 32 + l] = hi;
    }
}

// ---------------------------------------------------------------------------
// Kernel D: softmax; combines the two d-half partials, writes g_att.
// ---------------------------------------------------------------------------
__global__ __launch_bounds__(256) void k_softmax() {
    int row = blockIdx.x;
    int tx  = threadIdx.x;
    const float4* p0 = reinterpret_cast<const float4*>(g_attp[0] + (size_t)row * NN);
    const float4* p1 = reinterpret_cast<const float4*>(g_attp[1] + (size_t)row * NN);
    float4* pv = reinterpret_cast<float4*>(g_att + (size_t)row * NN);

    float4 x[4];
#pragma unroll
    for (int i = 0; i < 4; i++) {
        float4 a = p0[i * 256 + tx];
        float4 c = p1[i * 256 + tx];
        x[i] = make_float4(a.x + c.x, a.y + c.y, a.z + c.z, a.w + c.w);
    }

    float m = -3e38f;
#pragma unroll
    for (int i = 0; i < 4; i++)
        m = fmaxf(m, fmaxf(fmaxf(x[i].x, x[i].y), fmaxf(x[i].z, x[i].w)));
    __shared__ float r1[8], r2[8];
#pragma unroll
    for (int o = 16; o; o >>= 1) m = fmaxf(m, __shfl_xor_sync(0xffffffffu, m, o));
    if ((tx & 31) == 0) r1[tx >> 5] = m;
    __syncthreads();
    float bm = r1[0];
#pragma unroll
    for (int w = 1; w < 8; w++) bm = fmaxf(bm, r1[w]);

    float s = 0.f;
#pragma unroll
    for (int i = 0; i < 4; i++) {
        x[i].x = __expf(x[i].x - bm);
        x[i].y = __expf(x[i].y - bm);
        x[i].z = __expf(x[i].z - bm);
        x[i].w = __expf(x[i].w - bm);
        s += x[i].x + x[i].y + x[i].z + x[i].w;
    }
#pragma unroll
    for (int o = 16; o; o >>= 1) s += __shfl_xor_sync(0xffffffffu, s, o);
    if ((tx & 31) == 0) r2[tx >> 5] = s;
    __syncthreads();
    float tot = 0.f;
#pragma unroll
    for (int w = 0; w < 8; w++) tot += r2[w];
    float inv = 1.f / tot;
#pragma unroll
    for (int i = 0; i < 4; i++) {
        x[i].x *= inv; x[i].y *= inv; x[i].z *= inv; x[i].w *= inv;
        pv[i * 256 + tx] = x[i];
    }
}

// ---------------------------------------------------------------------------
// Kernel E: wp[seg][b,h,d] = sum_{n in seg(256)} attn[b,h,n] * value[b,n,d]
// grid (4 d-tiles of 256, 16 seg, 32 b) = 2048 CTAs, 128 thr; thread owns
// d, d+1 (float2 coalesced value loads). acc = 16 u64. launch_bounds(128,6).
// ---------------------------------------------------------------------------
__global__ __launch_bounds__(128, 6) void k_wpart(const float* __restrict__ value) {
    const int tx  = threadIdx.x;
    const int d0  = blockIdx.x * 256;
    const int seg = blockIdx.y;
    const int b   = blockIdx.z;
    const int d   = d0 + tx * 2;

    __shared__ __align__(16) float sA[256 * 20];   // [n][16h + 4 pad], 20KB

    const float* attb = g_att + (size_t)b * HH * NN + seg * 256;
#pragma unroll
    for (int i = 0; i < 8; i++) {
        int fl = i * 128 + tx;          // 1024 float4 of the slab
        int h = fl >> 6, n4 = (fl & 63) * 4;
        float4 a = *(const float4*)(attb + (size_t)h * NN + n4);
        sA[(n4 + 0) * 20 + h] = a.x;
        sA[(n4 + 1) * 20 + h] = a.y;
        sA[(n4 + 2) * 20 + h] = a.z;
        sA[(n4 + 3) * 20 + h] = a.w;
    }
    __syncthreads();

    u64 acc0[8], acc1[8];               // [hp] for d and d+1
#pragma unroll
    for (int p = 0; p < 8; p++) { acc0[p] = 0ull; acc1[p] = 0ull; }

    const float* vp = value + ((size_t)b * NN + seg * 256) * DD + d;

    float2 vc[4], vn[4];
#pragma unroll
    for (int j = 0; j < 4; j++)
        vc[j] = *(const float2*)(vp + (size_t)j * DD);

#pragma unroll 1
    for (int n = 0; n < 256; n += 4) {
        if (n + 4 < 256) {
#pragma unroll
            for (int j = 0; j < 4; j++)
                vn[j] = *(const float2*)(vp + (size_t)(n + 4 + j) * DD);
        }
#pragma unroll
        for (int j = 0; j < 4; j++) {
            u64 v0 = pack2(vc[j].x, vc[j].x);
            u64 v1 = pack2(vc[j].y, vc[j].y);
            const ulonglong2* av = (const ulonglong2*)&sA[(n + j) * 20];
            ulonglong2 a0 = av[0], a1 = av[1];
            fma2(acc0[0], a0.x, v0);  fma2(acc1[0], a0.x, v1);
            fma2(acc0[1], a0.y, v0);  fma2(acc1[1], a0.y, v1);
            fma2(acc0[2], a1.x, v0);  fma2(acc1[2], a1.x, v1);
            fma2(acc0[3], a1.y, v0);  fma2(acc1[3], a1.y, v1);
            ulonglong2 a2 = av[2], a3 = av[3];
            fma2(acc0[4], a2.x, v0);  fma2(acc1[4], a2.x, v1);
            fma2(acc0[5], a2.y, v0);  fma2(acc1[5], a2.y, v1);
            fma2(acc0[6], a3.x, v0);  fma2(acc1[6], a3.x, v1);
            fma2(acc0[7], a3.y, v0);  fma2(acc1[7], a3.y, v1);
        }
#pragma unroll
        for (int j = 0; j < 4; j++) vc[j] = vn[j];
    }

#pragma unroll
    for (int hp = 0; hp < 8; hp++) {
        float l0, h0, l1, h1;
        unpack2(acc0[hp], l0, h0);   // (head 2hp, head 2hp+1) at d
        unpack2(acc1[hp], l1, h1);   // (head 2hp, head 2hp+1) at d+1
        *(float2*)(g_wp[seg] + ((size_t)b * HH + 2 * hp)     * DD + d) = make_float2(l0, l1);
        *(float2*)(g_wp[seg] + ((size_t)b * HH + 2 * hp + 1) * DD + d) = make_float2(h0, h1);
    }
}

// ---------------------------------------------------------------------------
// Kernel F: out[b,c] += sum_{d in dsp-range(256)} w[b, c>>6, d] * wv[d, c]
// (w assembled on the fly from the 16 wpart partials)
// ---------------------------------------------------------------------------
__global__ __launch_bounds__(128) void k_oproj(const float* __restrict__ wv,
                                               float* __restrict__ out) {
    const int tx  = threadIdx.x;
    const int c0  = blockIdx.x * 128;
    const int b0  = blockIdx.y * 4;
    const int dsp = blockIdx.z;
    const int dr0 = dsp * 256;
    const int h0  = c0 >> 6;
    __shared__ __align__(16) float sw[4][2][256];

#pragma unroll
    for (int i = 0; i < 4; i++) {
        int fl = i * 128 + tx;
        int bb = fl >> 7, hh = (fl >> 6) & 1, d4 = fl & 63;
        size_t gidx = ((size_t)(b0 + bb) * HH + h0 + hh) * DD + dr0 + d4 * 4;
        float4 s = *(const float4*)(g_wp[0] + gidx);
#pragma unroll
        for (int p = 1; p < 16; p++) {
            float4 a = *(const float4*)(g_wp[p] + gidx);
            s.x += a.x; s.y += a.y; s.z += a.z; s.w += a.w;
        }
        *(float4*)&sw[bb][hh][d4 * 4] = s;
    }
    __syncthreads();

    const int hin = tx >> 6;
    u64 acc[4] = {0ull, 0ull, 0ull, 0ull};
    const float* wc = wv + (size_t)dr0 * DD + c0 + tx;
#pragma unroll 8
    for (int dd = 0; dd < 256; dd += 2) {
        float w0 = wc[(size_t)dd * DD];
        float w1 = wc[(size_t)(dd + 1) * DD];
        u64 w2 = pack2(w0, w1);
#pragma unroll
        for (int bb = 0; bb < 4; bb++) {
            u64 s2 = *(const u64*)&sw[bb][hin][dd];
            fma2(acc[bb], s2, w2);
        }
    }
#pragma unroll
    for (int bb = 0; bb < 4; bb++) {
        float lo, hi; unpack2(acc[bb], lo, hi);
        atomicAdd(&out[(size_t)(b0 + bb) * DD + c0 + tx], lo + hi);
    }
}

// ---------------------------------------------------------------------------
extern "C" void kernel_launch(void* const* d_in, const int* in_sizes, int n_in,
                              void* d_out, int out_size) {
    const float* query = (const float*)d_in[0];
    const float* key   = (const float*)d_in[1];
    const float* value = (const float*)d_in[2];
    const float* wq    = (const float*)d_in[3];
    const float* wk    = (const float*)d_in[4];
    const float* wv    = (const float*)d_in[5];
    float* out = (float*)d_out;

    k_qproj  <<<dim3(8, 8, 4),   128>>>(query, wq);
    k_uproj  <<<dim3(8, HH),     128>>>(wk);
    k_zero   <<<32,              256>>>(out);
    k_scores <<<dim3(16, 2, BB), 128>>>(key);
    k_softmax<<<BB * HH,         256>>>();
    k_wpart  <<<dim3(4, 16, BB), 128>>>(value);
    k_oproj  <<<dim3(8, 8, 4),   128>>>(wv, out);
}

// round 7
// speedup vs baseline: 1.0889x; 1.0889x over previous
#include <cuda_runtime.h>

#define BB 32
#define NN 4096
#define DD 1024
#define HH 16

// Scratch (device globals)
__device__ float g_qp[4][BB * DD];          // q projection partials over 4 d-ranges
__device__ float g_Ut[BB * DD * HH];        // folded key vectors, transposed [b][d][h] (scaled 1/8)
__device__ float g_att[BB * HH * NN];       // scores -> attn (softmaxed in place)
__device__ float g_wp[8][BB * HH * DD];     // partial attn@value over 8 n-segments

typedef unsigned long long u64;

__device__ __forceinline__ void fma2(u64 &d, u64 a, u64 b) {
    asm("fma.rn.f32x2 %0, %1, %2, %0;" : "+l"(d) : "l"(a), "l"(b));
}
__device__ __forceinline__ u64 pack2(float lo, float hi) {
    u64 r; asm("mov.b64 %0, {%1, %2};" : "=l"(r) : "f"(lo), "f"(hi)); return r;
}
__device__ __forceinline__ void unpack2(u64 v, float &lo, float &hi) {
    asm("mov.b64 {%0, %1}, %2;" : "=f"(lo), "=f"(hi) : "l"(v));
}
__device__ __forceinline__ unsigned smem_u32(const void* p) {
    return (unsigned)__cvta_generic_to_shared(p);
}
__device__ __forceinline__ void cpasync16(unsigned dst, const void* src) {
    asm volatile("cp.async.cg.shared.global [%0], [%1], 16;\n" :: "r"(dst), "l"(src));
}
#define CP_COMMIT() asm volatile("cp.async.commit_group;\n" ::: "memory")
#define CP_WAIT(n)  asm volatile("cp.async.wait_group %0;\n" :: "n"(n) : "memory")

// ---------------------------------------------------------------------------
// Kernel A: qp[dsp][b,c] = sum_{d in dsp-range(256)} query[b,d] * wq[d,c]
// ---------------------------------------------------------------------------
__global__ __launch_bounds__(128) void k_qproj(const float* __restrict__ query,
                                               const float* __restrict__ wq) {
    const int tx  = threadIdx.x;
    const int c0  = blockIdx.x * 128;
    const int b0  = blockIdx.y * 4;
    const int dsp = blockIdx.z;
    const int dr0 = dsp * 256;

    __shared__ __align__(16) float sq[4][256];
#pragma unroll
    for (int i = 0; i < 2; i++) {
        int fl = i * 128 + tx;
        int bb = fl >> 6, d4 = fl & 63;
        *(float4*)&sq[bb][d4 * 4] =
            *(const float4*)(query + (size_t)(b0 + bb) * DD + dr0 + d4 * 4);
    }
    __syncthreads();

    u64 acc[4] = {0ull, 0ull, 0ull, 0ull};
    const float* wc = wq + (size_t)dr0 * DD + c0 + tx;
#pragma unroll 16
    for (int d = 0; d < 256; d += 2) {
        float w0 = wc[(size_t)d * DD];
        float w1 = wc[(size_t)(d + 1) * DD];
        u64 w2 = pack2(w0, w1);
#pragma unroll
        for (int bb = 0; bb < 4; bb++) {
            u64 q2 = *(const u64*)&sq[bb][d];
            fma2(acc[bb], q2, w2);
        }
    }
#pragma unroll
    for (int bb = 0; bb < 4; bb++) {
        float lo, hi; unpack2(acc[bb], lo, hi);
        g_qp[dsp][(size_t)(b0 + bb) * DD + c0 + tx] = lo + hi;
    }
}

// ---------------------------------------------------------------------------
// Kernel B: Ut[b,d,h] = (1/8) * sum_{c<64} wk[d, h*64+c] * q[b, h*64+c]
// ---------------------------------------------------------------------------
__global__ __launch_bounds__(128) void k_uproj(const float* __restrict__ wk) {
    const int tx = threadIdx.x;
    const int d0 = blockIdx.x * 128;
    const int h  = blockIdx.y;
    __shared__ __align__(16) float4 swk4[128 * 17];
    __shared__ __align__(16) float  sq[32][64];

#pragma unroll
    for (int i = 0; i < 16; i++) {
        int fl = i * 128 + tx;
        int r  = fl >> 4, c4 = fl & 15;
        swk4[r * 17 + c4] =
            *(const float4*)(wk + (size_t)(d0 + r) * DD + h * 64 + c4 * 4);
    }
#pragma unroll
    for (int i = 0; i < 4; i++) {
        int fl = i * 128 + tx;
        int bb = fl >> 4, c4 = fl & 15;
        float4 s = *(const float4*)(g_qp[0] + (size_t)bb * DD + h * 64 + c4 * 4);
#pragma unroll
        for (int p = 1; p < 4; p++) {
            float4 a = *(const float4*)(g_qp[p] + (size_t)bb * DD + h * 64 + c4 * 4);
            s.x += a.x; s.y += a.y; s.z += a.z; s.w += a.w;
        }
        *(float4*)&sq[bb][c4 * 4] = s;
    }
    __syncthreads();

    ulonglong2 wreg[16];
#pragma unroll
    for (int c4 = 0; c4 < 16; c4++)
        wreg[c4] = *(const ulonglong2*)&swk4[tx * 17 + c4];

    const int dst_base = (d0 + tx) * HH + h;
#pragma unroll 2
    for (int bb = 0; bb < 32; bb++) {
        u64 a2 = 0ull;
#pragma unroll
        for (int c4 = 0; c4 < 16; c4++) {
            ulonglong2 q2 = *(const ulonglong2*)&sq[bb][c4 * 4];
            fma2(a2, wreg[c4].x, q2.x);
            fma2(a2, wreg[c4].y, q2.y);
        }
        float lo, hi; unpack2(a2, lo, hi);
        g_Ut[(size_t)bb * (DD * HH) + dst_base] = (lo + hi) * 0.125f;
    }
}

// ---------------------------------------------------------------------------
// Kernel Z: zero d_out (keeps k_scores in the profiled launch slot #4).
// ---------------------------------------------------------------------------
__global__ __launch_bounds__(256) void k_zero(float* __restrict__ out) {
    int i = blockIdx.x * 256 + threadIdx.x;
    reinterpret_cast<float4*>(out)[i] = make_float4(0.f, 0.f, 0.f, 0.f);
}

// ---------------------------------------------------------------------------
// Kernel C: scores[b,h,n] = sum_d key[b,n,d] * Ut[b,d,h]   (streams key 512MB)
// v4: 64-thread CTAs (2 warps). Warp owns 128 n; THREAD OWNS 4 n
// (l, l+32, l+64, l+96) -> every broadcast U load feeds 4x FMA2 work:
// per 16-d chunk/thread: 512 FMA2 vs 16 kv-LDS + 64 uv-LDS (86% FMA2 mix).
// Per-warp private slabs + U replica; cp.async double buffer; warp-sync only.
// ---------------------------------------------------------------------------
__global__ __launch_bounds__(64, 5) void k_scores(const float* __restrict__ key) {
    const int tx   = threadIdx.x;
    const int w    = tx >> 5;
    const int l    = tx & 31;
    const int b    = blockIdx.y;
    const int n0   = blockIdx.x * 256;
    const int nwrp = n0 + w * 128;

    // key slab: [128 n][4 data f4 + 1 pad] -> row stride 5 f4; 5l mod 8 is a
    // bijection -> conflict-free LDS.128 at rows l+32k. 40KB total.
    __shared__ __align__(16) float4 skW[2][2][128 * 5];
    // U chunk replica per warp: [16 d][16 h] floats = 64 f4 per stage. 4KB.
    __shared__ __align__(16) float4 sUW[2][2][64];

    const float* keyw = key + ((size_t)b * NN + nwrp) * DD;
    const float* Utb  = g_Ut + (size_t)b * (DD * HH);

    u64 acc[4][8];
#pragma unroll
    for (int n4 = 0; n4 < 4; n4++)
#pragma unroll
        for (int p = 0; p < 8; p++) acc[n4][p] = 0ull;

    // prologue: stage chunk 0 (d 0..15)
    {
#pragma unroll
        for (int i = 0; i < 16; i++) {
            int fl = i * 32 + l;
            int n = fl >> 2, q4 = fl & 3;
            cpasync16(smem_u32(&skW[w][0][n * 5 + q4]),
                      keyw + (size_t)n * DD + q4 * 4);
        }
#pragma unroll
        for (int j = 0; j < 2; j++)
            cpasync16(smem_u32(&sUW[w][0][j * 32 + l]), Utb + (j * 32 + l) * 4);
        CP_COMMIT();
    }

#pragma unroll 1
    for (int ch = 0; ch < 64; ch++) {
        if (ch + 1 < 64) {
            const int st = (ch + 1) & 1, d0 = (ch + 1) * 16;
#pragma unroll
            for (int i = 0; i < 16; i++) {
                int fl = i * 32 + l;
                int n = fl >> 2, q4 = fl & 3;
                cpasync16(smem_u32(&skW[w][st][n * 5 + q4]),
                          keyw + (size_t)n * DD + d0 + q4 * 4);
            }
#pragma unroll
            for (int j = 0; j < 2; j++)
                cpasync16(smem_u32(&sUW[w][st][j * 32 + l]),
                          Utb + d0 * HH + (j * 32 + l) * 4);
            CP_COMMIT();
            CP_WAIT(1);
        } else {
            CP_WAIT(0);
        }
        __syncwarp();

        const int st = ch & 1;
#pragma unroll
        for (int g = 0; g < 4; g++) {
            // one f4 of key per owned n (4 LDS.128, conflict-free)
            float4 kv[4];
#pragma unroll
            for (int n4 = 0; n4 < 4; n4++)
                kv[n4] = skW[w][st][(n4 * 32 + l) * 5 + g];
#pragma unroll
            for (int s = 0; s < 4; s++) {
                int dd = g * 4 + s;
                const ulonglong2* uv = (const ulonglong2*)&sUW[w][st][dd * 4];
                ulonglong2 u0 = uv[0], u1 = uv[1];
                ulonglong2 u2 = uv[2], u3 = uv[3];
#pragma unroll
                for (int n4 = 0; n4 < 4; n4++) {
                    float kvs = (s == 0) ? kv[n4].x : (s == 1) ? kv[n4].y
                              : (s == 2) ? kv[n4].z : kv[n4].w;
                    u64 kv2 = pack2(kvs, kvs);
                    fma2(acc[n4][0], u0.x, kv2);
                    fma2(acc[n4][1], u0.y, kv2);
                    fma2(acc[n4][2], u1.x, kv2);
                    fma2(acc[n4][3], u1.y, kv2);
                    fma2(acc[n4][4], u2.x, kv2);
                    fma2(acc[n4][5], u2.y, kv2);
                    fma2(acc[n4][6], u3.x, kv2);
                    fma2(acc[n4][7], u3.y, kv2);
                }
            }
        }
        __syncwarp();
    }

#pragma unroll
    for (int n4 = 0; n4 < 4; n4++) {
#pragma unroll
        for (int p = 0; p < 8; p++) {
            float lo, hi;
            unpack2(acc[n4][p], lo, hi);
            g_att[((size_t)b * HH + 2 * p)     * NN + nwrp + n4 * 32 + l] = lo;
            g_att[((size_t)b * HH + 2 * p + 1) * NN + nwrp + n4 * 32 + l] = hi;
        }
    }
}

// ---------------------------------------------------------------------------
// Kernel D: in-place softmax over N per (b,h) row.
// ---------------------------------------------------------------------------
__global__ __launch_bounds__(256) void k_softmax() {
    int row = blockIdx.x;
    int tx  = threadIdx.x;
    float4* pv = reinterpret_cast<float4*>(g_att + (size_t)row * NN);

    float4 x[4];
#pragma unroll
    for (int i = 0; i < 4; i++) x[i] = pv[i * 256 + tx];

    float m = -3e38f;
#pragma unroll
    for (int i = 0; i < 4; i++)
        m = fmaxf(m, fmaxf(fmaxf(x[i].x, x[i].y), fmaxf(x[i].z, x[i].w)));
    __shared__ float r1[8], r2[8];
#pragma unroll
    for (int o = 16; o; o >>= 1) m = fmaxf(m, __shfl_xor_sync(0xffffffffu, m, o));
    if ((tx & 31) == 0) r1[tx >> 5] = m;
    __syncthreads();
    float bm = r1[0];
#pragma unroll
    for (int w = 1; w < 8; w++) bm = fmaxf(bm, r1[w]);

    float s = 0.f;
#pragma unroll
    for (int i = 0; i < 4; i++) {
        x[i].x = __expf(x[i].x - bm);
        x[i].y = __expf(x[i].y - bm);
        x[i].z = __expf(x[i].z - bm);
        x[i].w = __expf(x[i].w - bm);
        s += x[i].x + x[i].y + x[i].z + x[i].w;
    }
#pragma unroll
    for (int o = 16; o; o >>= 1) s += __shfl_xor_sync(0xffffffffu, s, o);
    if ((tx & 31) == 0) r2[tx >> 5] = s;
    __syncthreads();
    float tot = 0.f;
#pragma unroll
    for (int w = 0; w < 8; w++) tot += r2[w];
    float inv = 1.f / tot;
#pragma unroll
    for (int i = 0; i < 4; i++) {
        x[i].x *= inv; x[i].y *= inv; x[i].z *= inv; x[i].w *= inv;
        pv[i * 256 + tx] = x[i];
    }
}

// ---------------------------------------------------------------------------
// Kernel E: wp[seg][b,h,d] = sum_{n in seg(512)} attn[b,h,n] * value[b,n,d]
// grid (2 d-tiles of 512, 8 seg, 32 b), 128 thr; thread owns 4 consecutive d
// (float4 LDG.128 of value). 86% FMA2 mix already. (R5 proven version.)
// ---------------------------------------------------------------------------
__global__ __launch_bounds__(128) void k_wpart(const float* __restrict__ value) {
    const int tx  = threadIdx.x;
    const int d0  = blockIdx.x * 512;
    const int seg = blockIdx.y;
    const int b   = blockIdx.z;

    __shared__ __align__(16) float sA[512 * 20];   // [n][16h + 4 pad], 40KB

    const float* attb = g_att + (size_t)b * HH * NN + seg * 512;
#pragma unroll
    for (int i = 0; i < 16; i++) {
        int fl = i * 128 + tx;
        int h = fl >> 7, n4 = (fl & 127) * 4;
        float4 a = *(const float4*)(attb + (size_t)h * NN + n4);
        sA[(n4 + 0) * 20 + h] = a.x;
        sA[(n4 + 1) * 20 + h] = a.y;
        sA[(n4 + 2) * 20 + h] = a.z;
        sA[(n4 + 3) * 20 + h] = a.w;
    }
    __syncthreads();

    u64 acc[32];   // acc[dd*8+hp], dd in 0..3 (4 owned d), hp in 0..7
#pragma unroll
    for (int p = 0; p < 32; p++) acc[p] = 0ull;

    const float* valb = value + ((size_t)b * NN + seg * 512) * DD + d0 + tx * 4;

    float4 vc[4], vn[4];
#pragma unroll
    for (int j = 0; j < 4; j++)
        vc[j] = *(const float4*)(valb + (size_t)j * DD);

#pragma unroll 1
    for (int n = 0; n < 512; n += 4) {
        if (n + 4 < 512) {
#pragma unroll
            for (int j = 0; j < 4; j++)
                vn[j] = *(const float4*)(valb + (size_t)(n + 4 + j) * DD);
        }
#pragma unroll
        for (int j = 0; j < 4; j++) {
            float vs[4] = {vc[j].x, vc[j].y, vc[j].z, vc[j].w};
            const ulonglong2* av = (const ulonglong2*)&sA[(n + j) * 20];
            ulonglong2 a0 = av[0], a1 = av[1], a2 = av[2], a3 = av[3];
#pragma unroll
            for (int dd = 0; dd < 4; dd++) {
                u64 v2 = pack2(vs[dd], vs[dd]);
                fma2(acc[dd * 8 + 0], a0.x, v2);
                fma2(acc[dd * 8 + 1], a0.y, v2);
                fma2(acc[dd * 8 + 2], a1.x, v2);
                fma2(acc[dd * 8 + 3], a1.y, v2);
                fma2(acc[dd * 8 + 4], a2.x, v2);
                fma2(acc[dd * 8 + 5], a2.y, v2);
                fma2(acc[dd * 8 + 6], a3.x, v2);
                fma2(acc[dd * 8 + 7], a3.y, v2);
            }
        }
#pragma unroll
        for (int j = 0; j < 4; j++) vc[j] = vn[j];
    }

#pragma unroll
    for (int hp = 0; hp < 8; hp++) {
        float l0, h0x, l1, h1x, l2, h2x, l3, h3x;
        unpack2(acc[0 * 8 + hp], l0, h0x);
        unpack2(acc[1 * 8 + hp], l1, h1x);
        unpack2(acc[2 * 8 + hp], l2, h2x);
        unpack2(acc[3 * 8 + hp], l3, h3x);
        float4 olo = make_float4(l0, l1, l2, l3);
        float4 ohi = make_float4(h0x, h1x, h2x, h3x);
        *(float4*)(g_wp[seg] + ((size_t)b * HH + 2 * hp)     * DD + d0 + tx * 4) = olo;
        *(float4*)(g_wp[seg] + ((size_t)b * HH + 2 * hp + 1) * DD + d0 + tx * 4) = ohi;
    }
}

// ---------------------------------------------------------------------------
// Kernel F: out[b,c] += sum_{d in dsp-range(256)} w[b, c>>6, d] * wv[d, c]
// (w assembled on the fly from the 8 wpart partials)
// ---------------------------------------------------------------------------
__global__ __launch_bounds__(128) void k_oproj(const float* __restrict__ wv,
                                               float* __restrict__ out) {
    const int tx  = threadIdx.x;
    const int c0  = blockIdx.x * 128;
    const int b0  = blockIdx.y * 4;
    const int dsp = blockIdx.z;
    const int dr0 = dsp * 256;
    const int h0  = c0 >> 6;
    __shared__ __align__(16) float sw[4][2][256];

#pragma unroll
    for (int i = 0; i < 4; i++) {
        int fl = i * 128 + tx;
        int bb = fl >> 7, hh = (fl >> 6) & 1, d4 = fl & 63;
        size_t gidx = ((size_t)(b0 + bb) * HH + h0 + hh) * DD + dr0 + d4 * 4;
        float4 s = *(const float4*)(g_wp[0] + gidx);
#pragma unroll
        for (int p = 1; p < 8; p++) {
            float4 a = *(const float4*)(g_wp[p] + gidx);
            s.x += a.x; s.y += a.y; s.z += a.z; s.w += a.w;
        }
        *(float4*)&sw[bb][hh][d4 * 4] = s;
    }
    __syncthreads();

    const int hin = tx >> 6;
    u64 acc[4] = {0ull, 0ull, 0ull, 0ull};
    const float* wc = wv + (size_t)dr0 * DD + c0 + tx;
#pragma unroll 16
    for (int dd = 0; dd < 256; dd += 2) {
        float w0 = wc[(size_t)dd * DD];
        float w1 = wc[(size_t)(dd + 1) * DD];
        u64 w2 = pack2(w0, w1);
#pragma unroll
        for (int bb = 0; bb < 4; bb++) {
            u64 s2 = *(const u64*)&sw[bb][hin][dd];
            fma2(acc[bb], s2, w2);
        }
    }
#pragma unroll
    for (int bb = 0; bb < 4; bb++) {
        float lo, hi; unpack2(acc[bb], lo, hi);
        atomicAdd(&out[(size_t)(b0 + bb) * DD + c0 + tx], lo + hi);
    }
}

// ---------------------------------------------------------------------------
extern "C" void kernel_launch(void* const* d_in, const int* in_sizes, int n_in,
                              void* d_out, int out_size) {
    const float* query = (const float*)d_in[0];
    const float* key   = (const float*)d_in[1];
    const float* value = (const float*)d_in[2];
    const float* wq    = (const float*)d_in[3];
    const float* wk    = (const float*)d_in[4];
    const float* wv    = (const float*)d_in[5];
    float* out = (float*)d_out;

    k_qproj  <<<dim3(8, 8, 4),  128>>>(query, wq);
    k_uproj  <<<dim3(8, HH),    128>>>(wk);
    k_zero   <<<32,             256>>>(out);
    k_scores <<<dim3(16, BB),   64>>>(key);
    k_softmax<<<BB * HH,        256>>>();
    k_wpart  <<<dim3(2, 8, BB), 128>>>(value);
    k_oproj  <<<dim3(8, 8, 4),  128>>>(wv, out);
}